// round 4
// baseline (speedup 1.0000x reference)
#include <cuda_runtime.h>
#include <math.h>

#define NN 50000
#define NE 800000
#define IND 64
#define ED 16
#define HID 128
#define GG 128
#define EPSV 1e-5f

// ---------------- scratch (no allocations allowed) ----------------
__device__ float d_h[(size_t)NN * HID];   // node features
__device__ float d_t[(size_t)NN * HID];   // aggr / mlp buffer
__device__ float d_g[GG * HID];           // pooled per-graph
__device__ int   d_off[GG + 1];           // graph segment offsets

// ---------------- graph offsets (batch is sorted int32) ----------------
__global__ void offsets_kernel(const int* __restrict__ batch) {
    int g = blockIdx.x * blockDim.x + threadIdx.x;
    if (g > GG) return;
    int lo = 0, hi = NN;
    while (lo < hi) {
        int mid = (lo + hi) >> 1;
        if (batch[mid] < g) lo = mid + 1; else hi = mid;
    }
    d_off[g] = lo;
}

// ---------------- aggr = h copy ----------------
__global__ void copy_kernel(const float4* __restrict__ src, float4* __restrict__ dst, int n4) {
    int i = blockIdx.x * blockDim.x + threadIdx.x;
    int stride = gridDim.x * blockDim.x;
    for (; i < n4; i += stride) dst[i] = src[i];
}

// ---------------- edge message + scatter ----------------
// one warp per edge: e = ea @ W + b ; msg = relu(h[src]+e) ; atomicAdd aggr[dst]
__global__ __launch_bounds__(256) void msg_kernel(
    const int* __restrict__ ei, const float* __restrict__ ea,
    const float* __restrict__ ew, const float* __restrict__ eb,
    const float* __restrict__ h, float* __restrict__ aggr)
{
    __shared__ float4 wS[ED][HID / 4];
    __shared__ float4 bS[HID / 4];
    int tid = threadIdx.x;
    for (int i = tid; i < ED * HID / 4; i += blockDim.x)
        wS[i / (HID / 4)][i % (HID / 4)] = ((const float4*)ew)[i];
    if (tid < HID / 4) bS[tid] = ((const float4*)eb)[tid];
    __syncthreads();

    int lane = tid & 31;
    int warp = tid >> 5;
    int gw = blockIdx.x * (blockDim.x >> 5) + warp;
    int nwarps = gridDim.x * (blockDim.x >> 5);

    for (int e = gw; e < NE; e += nwarps) {
        int src = ei[e];
        int dst = ei[NE + e];
        const float4* eav = (const float4*)(ea + (size_t)e * ED);
        float4 e0 = eav[0], e1 = eav[1], e2 = eav[2], e3 = eav[3];
        float a[16] = { e0.x, e0.y, e0.z, e0.w, e1.x, e1.y, e1.z, e1.w,
                        e2.x, e2.y, e2.z, e2.w, e3.x, e3.y, e3.z, e3.w };
        float4 acc = bS[lane];
        #pragma unroll
        for (int k = 0; k < 16; k++) {
            float4 w = wS[k][lane];
            acc.x += a[k] * w.x; acc.y += a[k] * w.y;
            acc.z += a[k] * w.z; acc.w += a[k] * w.w;
        }
        float4 hv = ((const float4*)(h + (size_t)src * HID))[lane];
        float mx = fmaxf(hv.x + acc.x, 0.f);
        float my = fmaxf(hv.y + acc.y, 0.f);
        float mz = fmaxf(hv.z + acc.z, 0.f);
        float mw = fmaxf(hv.w + acc.w, 0.f);
        float* ap = aggr + (size_t)dst * HID + lane * 4;
        atomicAdd(ap + 0, mx); atomicAdd(ap + 1, my);
        atomicAdd(ap + 2, mz); atomicAdd(ap + 3, mw);
    }
}

// ---------------- fused 2-layer MLP: out = [relu]( relu(in@W1+b1) @ W2 + b2 ) ----------------
// 128-row x 128-col tile per CTA, 8x8 register micro-tile per thread, 256 threads.
// MODE 0: write all rows. MODE 1: write rows where x[:,63] <= 0.5. MODE 2: where > 0.5.
template <int KD, int MODE, bool RELU_OUT>
__global__ __launch_bounds__(256) void mlp_kernel(
    const float* __restrict__ in, int nrows,
    const float* __restrict__ w1, const float* __restrict__ b1,
    const float* __restrict__ w2, const float* __restrict__ b2,
    const float* __restrict__ xflag,
    float* __restrict__ out)
{
    extern __shared__ float sm[];
    float* A = sm;               // input tile / h1 tile
    float* B = sm + HID * HID;   // weights
    const int tid = threadIdx.x;
    const int row0 = blockIdx.x * HID;

    // load input tile [128][KD]
    for (int i = tid; i < HID * KD / 4; i += 256) {
        int flat = i * 4;
        int r = flat / KD, k = flat - r * KD;
        float4 v = make_float4(0.f, 0.f, 0.f, 0.f);
        int gr = row0 + r;
        if (gr < nrows) v = *(const float4*)(in + (size_t)gr * KD + k);
        *(float4*)(A + r * KD + k) = v;
    }
    // load W1 [KD][128]
    for (int i = tid; i < KD * HID / 4; i += 256)
        ((float4*)B)[i] = ((const float4*)w1)[i];
    __syncthreads();

    const int tx = tid & 15, ty = tid >> 4;
    const int r0 = ty * 8, c0 = tx * 8;

    float acc[8][8];
    {
        float4 bb0 = *(const float4*)(b1 + c0);
        float4 bb1 = *(const float4*)(b1 + c0 + 4);
        float bj[8] = { bb0.x, bb0.y, bb0.z, bb0.w, bb1.x, bb1.y, bb1.z, bb1.w };
        #pragma unroll
        for (int i = 0; i < 8; i++)
            #pragma unroll
            for (int j = 0; j < 8; j++) acc[i][j] = bj[j];
    }
    #pragma unroll 4
    for (int k = 0; k < KD; k++) {
        float a[8];
        #pragma unroll
        for (int i = 0; i < 8; i++) a[i] = A[(r0 + i) * KD + k];
        float4 w0 = *(float4*)(B + k * HID + c0);
        float4 w1v = *(float4*)(B + k * HID + c0 + 4);
        float wj[8] = { w0.x, w0.y, w0.z, w0.w, w1v.x, w1v.y, w1v.z, w1v.w };
        #pragma unroll
        for (int i = 0; i < 8; i++)
            #pragma unroll
            for (int j = 0; j < 8; j++) acc[i][j] += a[i] * wj[j];
    }
    #pragma unroll
    for (int i = 0; i < 8; i++)
        #pragma unroll
        for (int j = 0; j < 8; j++) acc[i][j] = fmaxf(acc[i][j], 0.f);
    __syncthreads();  // all reads of A/B done

    // store h1 into A as [128][128]
    #pragma unroll
    for (int i = 0; i < 8; i++) {
        *(float4*)(A + (r0 + i) * HID + c0)     = make_float4(acc[i][0], acc[i][1], acc[i][2], acc[i][3]);
        *(float4*)(A + (r0 + i) * HID + c0 + 4) = make_float4(acc[i][4], acc[i][5], acc[i][6], acc[i][7]);
    }
    // load W2 [128][128]
    for (int i = tid; i < HID * HID / 4; i += 256)
        ((float4*)B)[i] = ((const float4*)w2)[i];
    __syncthreads();

    float acc2[8][8];
    {
        float4 bb0 = *(const float4*)(b2 + c0);
        float4 bb1 = *(const float4*)(b2 + c0 + 4);
        float bj[8] = { bb0.x, bb0.y, bb0.z, bb0.w, bb1.x, bb1.y, bb1.z, bb1.w };
        #pragma unroll
        for (int i = 0; i < 8; i++)
            #pragma unroll
            for (int j = 0; j < 8; j++) acc2[i][j] = bj[j];
    }
    #pragma unroll 4
    for (int k = 0; k < HID; k++) {
        float a[8];
        #pragma unroll
        for (int i = 0; i < 8; i++) a[i] = A[(r0 + i) * HID + k];
        float4 w0 = *(float4*)(B + k * HID + c0);
        float4 w1v = *(float4*)(B + k * HID + c0 + 4);
        float wj[8] = { w0.x, w0.y, w0.z, w0.w, w1v.x, w1v.y, w1v.z, w1v.w };
        #pragma unroll
        for (int i = 0; i < 8; i++)
            #pragma unroll
            for (int j = 0; j < 8; j++) acc2[i][j] += a[i] * wj[j];
    }
    if (RELU_OUT) {
        #pragma unroll
        for (int i = 0; i < 8; i++)
            #pragma unroll
            for (int j = 0; j < 8; j++) acc2[i][j] = fmaxf(acc2[i][j], 0.f);
    }
    #pragma unroll
    for (int i = 0; i < 8; i++) {
        int gr = row0 + r0 + i;
        if (gr >= nrows) continue;
        if (MODE == 1) { if (xflag[(size_t)gr * IND + (IND - 1)] > 0.5f) continue; }
        if (MODE == 2) { if (!(xflag[(size_t)gr * IND + (IND - 1)] > 0.5f)) continue; }
        *(float4*)(out + (size_t)gr * HID + c0)     = make_float4(acc2[i][0], acc2[i][1], acc2[i][2], acc2[i][3]);
        *(float4*)(out + (size_t)gr * HID + c0 + 4) = make_float4(acc2[i][4], acc2[i][5], acc2[i][6], acc2[i][7]);
    }
}

// ---------------- GraphNorm (+ optional global_add_pool) ----------------
__global__ __launch_bounds__(512) void gnorm_kernel(
    const float* __restrict__ in, float* __restrict__ out,
    const float* __restrict__ gw, const float* __restrict__ gb,
    const float* __restrict__ gms, int do_pool)
{
    __shared__ float red[4 * HID];
    __shared__ float stat[HID];
    int g = blockIdx.x;
    int tid = threadIdx.x;
    int c = tid & (HID - 1);
    int sub = tid >> 7;           // 0..3
    int s = d_off[g], e = d_off[g + 1];
    float cnt = fmaxf((float)(e - s), 1.f);

    float sum = 0.f;
    for (int n = s + sub; n < e; n += 4) sum += in[(size_t)n * HID + c];
    red[sub * HID + c] = sum;
    __syncthreads();
    if (sub == 0)
        stat[c] = (red[c] + red[HID + c] + red[2 * HID + c] + red[3 * HID + c]) / cnt * gms[c];
    __syncthreads();
    float mean = stat[c];

    float vs = 0.f;
    for (int n = s + sub; n < e; n += 4) {
        float hc = in[(size_t)n * HID + c] - mean;
        vs += hc * hc;
    }
    red[sub * HID + c] = vs;
    __syncthreads();
    if (sub == 0) {
        float var = (red[c] + red[HID + c] + red[2 * HID + c] + red[3 * HID + c]) / cnt;
        stat[c] = rsqrtf(var + EPSV);
    }
    __syncthreads();
    float w = gw[c] * stat[c];
    float b = gb[c];

    float pool = 0.f;
    for (int n = s + sub; n < e; n += 4) {
        float v = fmaxf((in[(size_t)n * HID + c] - mean) * w + b, 0.f);
        out[(size_t)n * HID + c] = v;
        pool += v;
    }
    if (do_pool) {
        __syncthreads();
        red[sub * HID + c] = pool;
        __syncthreads();
        if (sub == 0)
            d_g[g * HID + c] = red[c] + red[HID + c] + red[2 * HID + c] + red[3 * HID + c];
    }
}

// ---------------- output head ----------------
__global__ __launch_bounds__(128) void head_kernel(
    const float* __restrict__ fw1, const float* __restrict__ fb1,
    const float* __restrict__ fw2, const float* __restrict__ fb2,
    float* __restrict__ outp)
{
    int i = blockIdx.x;
    int c = threadIdx.x;
    __shared__ float gs[HID];
    __shared__ float red[HID];
    gs[c] = d_g[i * HID + c];
    __syncthreads();
    float acc = fb1[c];
    #pragma unroll 4
    for (int k = 0; k < HID; k++) acc += gs[k] * fw1[k * HID + c];
    red[c] = fmaxf(acc, 0.f) * fw2[c];
    __syncthreads();
    for (int s = 64; s > 0; s >>= 1) {
        if (c < s) red[c] += red[c + s];
        __syncthreads();
    }
    if (c == 0) outp[i] = red[0] + fb2[0];
}

// ---------------- launch ----------------
extern "C" void kernel_launch(void* const* d_in, const int* in_sizes, int n_in,
                              void* d_out, int out_size)
{
    const float* x     = (const float*)d_in[0];
    const int*   ei    = (const int*)d_in[1];     // int32 (JAX x64 disabled)
    const float* ea    = (const float*)d_in[2];
    const int*   batch = (const int*)d_in[3];     // int32
    const float* lig_w1 = (const float*)d_in[4];
    const float* lig_b1 = (const float*)d_in[5];
    const float* lig_w2 = (const float*)d_in[6];
    const float* lig_b2 = (const float*)d_in[7];
    const float* prot_w1 = (const float*)d_in[8];
    const float* prot_b1 = (const float*)d_in[9];
    const float* prot_w2 = (const float*)d_in[10];
    const float* prot_b2 = (const float*)d_in[11];
    const float* edge_w = (const float*)d_in[12];
    const float* edge_b = (const float*)d_in[13];
    const float* nn_w1 = (const float*)d_in[14];
    const float* nn_b1 = (const float*)d_in[15];
    const float* nn_w2 = (const float*)d_in[16];
    const float* nn_b2 = (const float*)d_in[17];
    const float* gn_w = (const float*)d_in[18];
    const float* gn_b = (const float*)d_in[19];
    const float* gn_ms = (const float*)d_in[20];
    const float* fc_w1 = (const float*)d_in[21];
    const float* fc_b1 = (const float*)d_in[22];
    const float* fc_w2 = (const float*)d_in[23];
    const float* fc_b2 = (const float*)d_in[24];
    float* outp = (float*)d_out;

    float* hptr = nullptr; float* tptr = nullptr;
    cudaGetSymbolAddress((void**)&hptr, d_h);
    cudaGetSymbolAddress((void**)&tptr, d_t);

    const int SMEM_MLP = 2 * HID * HID * sizeof(float);  // 128 KB
    cudaFuncSetAttribute(mlp_kernel<IND, 1, true>,  cudaFuncAttributeMaxDynamicSharedMemorySize, SMEM_MLP);
    cudaFuncSetAttribute(mlp_kernel<IND, 2, true>,  cudaFuncAttributeMaxDynamicSharedMemorySize, SMEM_MLP);
    cudaFuncSetAttribute(mlp_kernel<HID, 0, false>, cudaFuncAttributeMaxDynamicSharedMemorySize, SMEM_MLP);

    offsets_kernel<<<1, 256>>>(batch);

    dim3 gB((NN + HID - 1) / HID);  // 391 blocks
    mlp_kernel<IND, 1, true><<<gB, 256, SMEM_MLP>>>(x, NN, lig_w1, lig_b1, lig_w2, lig_b2, x, hptr);
    mlp_kernel<IND, 2, true><<<gB, 256, SMEM_MLP>>>(x, NN, prot_w1, prot_b1, prot_w2, prot_b2, x, hptr);

    const int n4 = NN * HID / 4;
    for (int l = 0; l < 3; l++) {
        copy_kernel<<<2048, 256>>>((const float4*)hptr, (float4*)tptr, n4);
        msg_kernel<<<1184, 256>>>(ei, ea, edge_w + (size_t)l * ED * HID, edge_b + (size_t)l * HID,
                                  hptr, tptr);
        mlp_kernel<HID, 0, false><<<gB, 256, SMEM_MLP>>>(
            tptr, NN,
            nn_w1 + (size_t)l * HID * HID, nn_b1 + (size_t)l * HID,
            nn_w2 + (size_t)l * HID * HID, nn_b2 + (size_t)l * HID,
            nullptr, tptr);
        gnorm_kernel<<<GG, 512>>>(tptr, hptr,
                                  gn_w + (size_t)l * HID, gn_b + (size_t)l * HID,
                                  gn_ms + (size_t)l * HID, (l == 2) ? 1 : 0);
    }

    head_kernel<<<GG, 128>>>(fc_w1, fc_b1, fc_w2, fc_b2, outp);
}

// round 6
// speedup vs baseline: 1.1147x; 1.1147x over previous
#include <cuda_runtime.h>
#include <cuda_bf16.h>
#include <stdint.h>
#include <math.h>

#define NN 50000
#define NE 800000
#define IND 64
#define ED 16
#define HID 128
#define GG 128
#define EPSV 1e-5f
#define ASTR 132   // padded smem row stride (bf16 elems): 264B rows -> conflict-free frags

// ---------------- scratch (no allocations allowed) ----------------
__device__ float d_h[(size_t)NN * HID];   // node features
__device__ float d_t[(size_t)NN * HID];   // aggr / mlp buffer
__device__ float d_g[GG * HID];           // pooled per-graph
__device__ int   d_off[GG + 1];           // graph segment offsets

// ---------------- graph offsets (batch is sorted int32) ----------------
__global__ void offsets_kernel(const int* __restrict__ batch) {
    int g = blockIdx.x * blockDim.x + threadIdx.x;
    if (g > GG) return;
    int lo = 0, hi = NN;
    while (lo < hi) {
        int mid = (lo + hi) >> 1;
        if (batch[mid] < g) lo = mid + 1; else hi = mid;
    }
    d_off[g] = lo;
}

// ---------------- edge message + scatter ----------------
__global__ __launch_bounds__(256) void msg_kernel(
    const int* __restrict__ ei, const float* __restrict__ ea,
    const float* __restrict__ ew, const float* __restrict__ eb,
    const float* __restrict__ h, float* __restrict__ aggr)
{
    __shared__ float4 wS[ED][HID / 4];
    __shared__ float4 bS[HID / 4];
    int tid = threadIdx.x;
    for (int i = tid; i < ED * HID / 4; i += blockDim.x)
        wS[i / (HID / 4)][i % (HID / 4)] = ((const float4*)ew)[i];
    if (tid < HID / 4) bS[tid] = ((const float4*)eb)[tid];
    __syncthreads();

    int lane = tid & 31;
    int warp = tid >> 5;
    int gw = blockIdx.x * (blockDim.x >> 5) + warp;
    int nwarps = gridDim.x * (blockDim.x >> 5);

    for (int e = gw; e < NE; e += nwarps) {
        int src = ei[e];
        int dst = ei[NE + e];
        const float4* eav = (const float4*)(ea + (size_t)e * ED);
        float4 e0 = eav[0], e1 = eav[1], e2 = eav[2], e3 = eav[3];
        float a[16] = { e0.x, e0.y, e0.z, e0.w, e1.x, e1.y, e1.z, e1.w,
                        e2.x, e2.y, e2.z, e2.w, e3.x, e3.y, e3.z, e3.w };
        float4 acc = bS[lane];
        #pragma unroll
        for (int k = 0; k < 16; k++) {
            float4 w = wS[k][lane];
            acc.x += a[k] * w.x; acc.y += a[k] * w.y;
            acc.z += a[k] * w.z; acc.w += a[k] * w.w;
        }
        float4 hv = ((const float4*)(h + (size_t)src * HID))[lane];
        float mx = fmaxf(hv.x + acc.x, 0.f);
        float my = fmaxf(hv.y + acc.y, 0.f);
        float mz = fmaxf(hv.z + acc.z, 0.f);
        float mw = fmaxf(hv.w + acc.w, 0.f);
        float* ap = aggr + (size_t)dst * HID + lane * 4;
        atomicAdd(ap + 0, mx); atomicAdd(ap + 1, my);
        atomicAdd(ap + 2, mz); atomicAdd(ap + 3, mw);
    }
}

// ---------------- bf16 split + mma helpers ----------------
__device__ __forceinline__ void bsplit(float x, __nv_bfloat16& h, __nv_bfloat16& l) {
    h = __float2bfloat16_rn(x);
    l = __float2bfloat16_rn(x - __bfloat162float(h));
}

__device__ __forceinline__ void mma_bf16(float c[4], const uint32_t a[4], const uint32_t b[2]) {
    asm volatile(
        "mma.sync.aligned.m16n8k16.row.col.f32.bf16.bf16.f32 "
        "{%0,%1,%2,%3}, {%4,%5,%6,%7}, {%8,%9}, {%0,%1,%2,%3};"
        : "+f"(c[0]), "+f"(c[1]), "+f"(c[2]), "+f"(c[3])
        : "r"(a[0]), "r"(a[1]), "r"(a[2]), "r"(a[3]), "r"(b[0]), "r"(b[1]));
}

// warp computes 32x64 of C += A[32 x 16*nch] * W^T, bf16x3 compensated.
// A: row-major [row][k] stride ASTR (hi/lo). W: transposed [n][k] stride ASTR (hi/lo).
__device__ __forceinline__ void warp_gemm(
    const __nv_bfloat16* __restrict__ Ah, const __nv_bfloat16* __restrict__ Al,
    const __nv_bfloat16* __restrict__ Wh, const __nv_bfloat16* __restrict__ Wl,
    int nch, int r0, int c0, int grp, int qp, float C[2][8][4])
{
    for (int ch = 0; ch < nch; ch++) {
        const int kc = ch * 16 + qp * 2;
        uint32_t ah[2][4], al[2][4];
        #pragma unroll
        for (int mt = 0; mt < 2; mt++) {
            const __nv_bfloat16* p = Ah + (r0 + mt * 16 + grp) * ASTR + kc;
            const __nv_bfloat16* q = Al + (r0 + mt * 16 + grp) * ASTR + kc;
            ah[mt][0] = *(const uint32_t*)p;
            ah[mt][1] = *(const uint32_t*)(p + 8 * ASTR);
            ah[mt][2] = *(const uint32_t*)(p + 8);
            ah[mt][3] = *(const uint32_t*)(p + 8 * ASTR + 8);
            al[mt][0] = *(const uint32_t*)q;
            al[mt][1] = *(const uint32_t*)(q + 8 * ASTR);
            al[mt][2] = *(const uint32_t*)(q + 8);
            al[mt][3] = *(const uint32_t*)(q + 8 * ASTR + 8);
        }
        #pragma unroll
        for (int nt = 0; nt < 8; nt++) {
            const __nv_bfloat16* p = Wh + (c0 + nt * 8 + grp) * ASTR + kc;
            const __nv_bfloat16* q = Wl + (c0 + nt * 8 + grp) * ASTR + kc;
            uint32_t bh[2] = { *(const uint32_t*)p, *(const uint32_t*)(p + 8) };
            uint32_t bl[2] = { *(const uint32_t*)q, *(const uint32_t*)(q + 8) };
            #pragma unroll
            for (int mt = 0; mt < 2; mt++) {
                mma_bf16(C[mt][nt], ah[mt], bh);
                mma_bf16(C[mt][nt], ah[mt], bl);
                mma_bf16(C[mt][nt], al[mt], bh);
            }
        }
    }
}

// ---------------- fused 2-layer MLP via tensor cores ----------------
// out = [relu]( relu(in@W1+b1) @ W2 + b2 ), 128x128 tile/CTA, 256 threads.
// MODE 0: write all rows. MODE 1: rows with x[:,63] <= 0.5. MODE 2: > 0.5.
template <int KD, int MODE, bool RELU_OUT>
__global__ __launch_bounds__(256) void mlp_mma(
    const float* __restrict__ in, int nrows,
    const float* __restrict__ w1, const float* __restrict__ b1,
    const float* __restrict__ w2, const float* __restrict__ b2,
    const float* __restrict__ xflag,
    float* __restrict__ out, float* __restrict__ out2)
{
    extern __shared__ __nv_bfloat16 smb[];
    __nv_bfloat16* Ah = smb;
    __nv_bfloat16* Al = Ah + 128 * ASTR;
    __nv_bfloat16* Wh = Al + 128 * ASTR;
    __nv_bfloat16* Wl = Wh + 128 * ASTR;

    const int tid = threadIdx.x;
    const int row0 = blockIdx.x * 128;

    // load input tile [128][KD] fp32 -> bf16 hi/lo
    for (int i = tid; i < 128 * (KD / 4); i += 256) {
        int r = i / (KD / 4), k4 = (i % (KD / 4)) * 4;
        float4 v = make_float4(0.f, 0.f, 0.f, 0.f);
        int gr = row0 + r;
        if (gr < nrows) v = *(const float4*)(in + (size_t)gr * KD + k4);
        __nv_bfloat16 h0, l0, h1, l1, h2, l2, h3, l3;
        bsplit(v.x, h0, l0); bsplit(v.y, h1, l1);
        bsplit(v.z, h2, l2); bsplit(v.w, h3, l3);
        *(__nv_bfloat162*)&Ah[r * ASTR + k4]     = __halves2bfloat162(h0, h1);
        *(__nv_bfloat162*)&Ah[r * ASTR + k4 + 2] = __halves2bfloat162(h2, h3);
        *(__nv_bfloat162*)&Al[r * ASTR + k4]     = __halves2bfloat162(l0, l1);
        *(__nv_bfloat162*)&Al[r * ASTR + k4 + 2] = __halves2bfloat162(l2, l3);
    }
    // load W1 [KD][128] transposed -> Wt[n][k]
    for (int i = tid; i < KD * 32; i += 256) {
        int k = i / 32, n = (i % 32) * 4;
        float4 v = *(const float4*)(w1 + (size_t)k * HID + n);
        __nv_bfloat16 h, l;
        bsplit(v.x, h, l); Wh[(n + 0) * ASTR + k] = h; Wl[(n + 0) * ASTR + k] = l;
        bsplit(v.y, h, l); Wh[(n + 1) * ASTR + k] = h; Wl[(n + 1) * ASTR + k] = l;
        bsplit(v.z, h, l); Wh[(n + 2) * ASTR + k] = h; Wl[(n + 2) * ASTR + k] = l;
        bsplit(v.w, h, l); Wh[(n + 3) * ASTR + k] = h; Wl[(n + 3) * ASTR + k] = l;
    }
    __syncthreads();

    const int lane = tid & 31, wid = tid >> 5;
    const int r0 = (wid & 3) * 32, c0 = (wid >> 2) * 64;
    const int grp = lane >> 2, qp = lane & 3;

    float C[2][8][4];
    #pragma unroll
    for (int nt = 0; nt < 8; nt++) {
        float2 bv = *(const float2*)(b1 + c0 + nt * 8 + qp * 2);
        #pragma unroll
        for (int mt = 0; mt < 2; mt++) {
            C[mt][nt][0] = bv.x; C[mt][nt][1] = bv.y;
            C[mt][nt][2] = bv.x; C[mt][nt][3] = bv.y;
        }
    }
    warp_gemm(Ah, Al, Wh, Wl, KD / 16, r0, c0, grp, qp, C);
    __syncthreads();   // all GEMM1 smem reads done

    // write relu(h1) back into Ah/Al as new A [128][128]
    #pragma unroll
    for (int mt = 0; mt < 2; mt++) {
        int row = r0 + mt * 16 + grp;
        #pragma unroll
        for (int nt = 0; nt < 8; nt++) {
            int col = c0 + nt * 8 + qp * 2;
            float v0 = fmaxf(C[mt][nt][0], 0.f), v1 = fmaxf(C[mt][nt][1], 0.f);
            float v2 = fmaxf(C[mt][nt][2], 0.f), v3 = fmaxf(C[mt][nt][3], 0.f);
            __nv_bfloat16 ha, la, hb, lb;
            bsplit(v0, ha, la); bsplit(v1, hb, lb);
            *(__nv_bfloat162*)&Ah[row * ASTR + col] = __halves2bfloat162(ha, hb);
            *(__nv_bfloat162*)&Al[row * ASTR + col] = __halves2bfloat162(la, lb);
            bsplit(v2, ha, la); bsplit(v3, hb, lb);
            *(__nv_bfloat162*)&Ah[(row + 8) * ASTR + col] = __halves2bfloat162(ha, hb);
            *(__nv_bfloat162*)&Al[(row + 8) * ASTR + col] = __halves2bfloat162(la, lb);
        }
    }
    // load W2 [128][128] transposed
    for (int i = tid; i < HID * 32; i += 256) {
        int k = i / 32, n = (i % 32) * 4;
        float4 v = *(const float4*)(w2 + (size_t)k * HID + n);
        __nv_bfloat16 h, l;
        bsplit(v.x, h, l); Wh[(n + 0) * ASTR + k] = h; Wl[(n + 0) * ASTR + k] = l;
        bsplit(v.y, h, l); Wh[(n + 1) * ASTR + k] = h; Wl[(n + 1) * ASTR + k] = l;
        bsplit(v.z, h, l); Wh[(n + 2) * ASTR + k] = h; Wl[(n + 2) * ASTR + k] = l;
        bsplit(v.w, h, l); Wh[(n + 3) * ASTR + k] = h; Wl[(n + 3) * ASTR + k] = l;
    }
    __syncthreads();

    #pragma unroll
    for (int nt = 0; nt < 8; nt++) {
        float2 bv = *(const float2*)(b2 + c0 + nt * 8 + qp * 2);
        #pragma unroll
        for (int mt = 0; mt < 2; mt++) {
            C[mt][nt][0] = bv.x; C[mt][nt][1] = bv.y;
            C[mt][nt][2] = bv.x; C[mt][nt][3] = bv.y;
        }
    }
    warp_gemm(Ah, Al, Wh, Wl, HID / 16, r0, c0, grp, qp, C);

    // store
    #pragma unroll
    for (int mt = 0; mt < 2; mt++) {
        #pragma unroll
        for (int rh = 0; rh < 2; rh++) {
            int gr = row0 + r0 + mt * 16 + grp + rh * 8;
            if (gr >= nrows) continue;
            if (MODE == 1) { if (xflag[(size_t)gr * IND + (IND - 1)] > 0.5f) continue; }
            if (MODE == 2) { if (!(xflag[(size_t)gr * IND + (IND - 1)] > 0.5f)) continue; }
            #pragma unroll
            for (int nt = 0; nt < 8; nt++) {
                int col = c0 + nt * 8 + qp * 2;
                float v0 = C[mt][nt][rh * 2 + 0], v1 = C[mt][nt][rh * 2 + 1];
                if (RELU_OUT) { v0 = fmaxf(v0, 0.f); v1 = fmaxf(v1, 0.f); }
                float2 o = make_float2(v0, v1);
                *(float2*)(out + (size_t)gr * HID + col) = o;
                if (out2) *(float2*)(out2 + (size_t)gr * HID + col) = o;
            }
        }
    }
}

// ---------------- GraphNorm (+ optional pool, + seed next-layer aggr) ----------------
__global__ __launch_bounds__(512) void gnorm_kernel(
    const float* __restrict__ in, float* __restrict__ out,
    float* __restrict__ out2,
    const float* __restrict__ gw, const float* __restrict__ gb,
    const float* __restrict__ gms, int do_pool)
{
    __shared__ float red[4 * HID];
    __shared__ float stat[HID];
    int g = blockIdx.x;
    int tid = threadIdx.x;
    int c = tid & (HID - 1);
    int sub = tid >> 7;
    int s = d_off[g], e = d_off[g + 1];
    float cnt = fmaxf((float)(e - s), 1.f);

    float sum = 0.f;
    for (int n = s + sub; n < e; n += 4) sum += in[(size_t)n * HID + c];
    red[sub * HID + c] = sum;
    __syncthreads();
    if (sub == 0)
        stat[c] = (red[c] + red[HID + c] + red[2 * HID + c] + red[3 * HID + c]) / cnt * gms[c];
    __syncthreads();
    float mean = stat[c];

    float vs = 0.f;
    for (int n = s + sub; n < e; n += 4) {
        float hc = in[(size_t)n * HID + c] - mean;
        vs += hc * hc;
    }
    red[sub * HID + c] = vs;
    __syncthreads();
    if (sub == 0) {
        float var = (red[c] + red[HID + c] + red[2 * HID + c] + red[3 * HID + c]) / cnt;
        stat[c] = rsqrtf(var + EPSV);
    }
    __syncthreads();
    float w = gw[c] * stat[c];
    float b = gb[c];

    float pool = 0.f;
    for (int n = s + sub; n < e; n += 4) {
        float v = fmaxf((in[(size_t)n * HID + c] - mean) * w + b, 0.f);
        out[(size_t)n * HID + c] = v;
        if (out2) out2[(size_t)n * HID + c] = v;
        pool += v;
    }
    if (do_pool) {
        __syncthreads();
        red[sub * HID + c] = pool;
        __syncthreads();
        if (sub == 0)
            d_g[g * HID + c] = red[c] + red[HID + c] + red[2 * HID + c] + red[3 * HID + c];
    }
}

// ---------------- output head ----------------
__global__ __launch_bounds__(128) void head_kernel(
    const float* __restrict__ fw1, const float* __restrict__ fb1,
    const float* __restrict__ fw2, const float* __restrict__ fb2,
    float* __restrict__ outp)
{
    int i = blockIdx.x;
    int c = threadIdx.x;
    __shared__ float gs[HID];
    __shared__ float red[HID];
    gs[c] = d_g[i * HID + c];
    __syncthreads();
    float acc = fb1[c];
    #pragma unroll 4
    for (int k = 0; k < HID; k++) acc += gs[k] * fw1[k * HID + c];
    red[c] = fmaxf(acc, 0.f) * fw2[c];
    __syncthreads();
    for (int s = 64; s > 0; s >>= 1) {
        if (c < s) red[c] += red[c + s];
        __syncthreads();
    }
    if (c == 0) outp[i] = red[0] + fb2[0];
}

// ---------------- launch ----------------
extern "C" void kernel_launch(void* const* d_in, const int* in_sizes, int n_in,
                              void* d_out, int out_size)
{
    const float* x     = (const float*)d_in[0];
    const int*   ei    = (const int*)d_in[1];
    const float* ea    = (const float*)d_in[2];
    const int*   batch = (const int*)d_in[3];
    const float* lig_w1 = (const float*)d_in[4];
    const float* lig_b1 = (const float*)d_in[5];
    const float* lig_w2 = (const float*)d_in[6];
    const float* lig_b2 = (const float*)d_in[7];
    const float* prot_w1 = (const float*)d_in[8];
    const float* prot_b1 = (const float*)d_in[9];
    const float* prot_w2 = (const float*)d_in[10];
    const float* prot_b2 = (const float*)d_in[11];
    const float* edge_w = (const float*)d_in[12];
    const float* edge_b = (const float*)d_in[13];
    const float* nn_w1 = (const float*)d_in[14];
    const float* nn_b1 = (const float*)d_in[15];
    const float* nn_w2 = (const float*)d_in[16];
    const float* nn_b2 = (const float*)d_in[17];
    const float* gn_w = (const float*)d_in[18];
    const float* gn_b = (const float*)d_in[19];
    const float* gn_ms = (const float*)d_in[20];
    const float* fc_w1 = (const float*)d_in[21];
    const float* fc_b1 = (const float*)d_in[22];
    const float* fc_w2 = (const float*)d_in[23];
    const float* fc_b2 = (const float*)d_in[24];
    float* outp = (float*)d_out;

    float* hptr = nullptr; float* tptr = nullptr;
    cudaGetSymbolAddress((void**)&hptr, d_h);
    cudaGetSymbolAddress((void**)&tptr, d_t);

    const int SMEM_MLP = 4 * 128 * ASTR * (int)sizeof(__nv_bfloat16);  // 135168 B
    cudaFuncSetAttribute(mlp_mma<IND, 1, true>,  cudaFuncAttributeMaxDynamicSharedMemorySize, SMEM_MLP);
    cudaFuncSetAttribute(mlp_mma<IND, 2, true>,  cudaFuncAttributeMaxDynamicSharedMemorySize, SMEM_MLP);
    cudaFuncSetAttribute(mlp_mma<HID, 0, false>, cudaFuncAttributeMaxDynamicSharedMemorySize, SMEM_MLP);

    offsets_kernel<<<1, 256>>>(batch);

    dim3 gB((NN + 127) / 128);  // 391 blocks
    // encoders: write h AND seed aggr buffer (t) with h
    mlp_mma<IND, 1, true><<<gB, 256, SMEM_MLP>>>(x, NN, lig_w1, lig_b1, lig_w2, lig_b2, x, hptr, tptr);
    mlp_mma<IND, 2, true><<<gB, 256, SMEM_MLP>>>(x, NN, prot_w1, prot_b1, prot_w2, prot_b2, x, hptr, tptr);

    for (int l = 0; l < 3; l++) {
        msg_kernel<<<1184, 256>>>(ei, ea, edge_w + (size_t)l * ED * HID, edge_b + (size_t)l * HID,
                                  hptr, tptr);
        mlp_mma<HID, 0, false><<<gB, 256, SMEM_MLP>>>(
            tptr, NN,
            nn_w1 + (size_t)l * HID * HID, nn_b1 + (size_t)l * HID,
            nn_w2 + (size_t)l * HID * HID, nn_b2 + (size_t)l * HID,
            nullptr, tptr, nullptr);
        gnorm_kernel<<<GG, 512>>>(tptr, hptr, (l < 2) ? tptr : nullptr,
                                  gn_w + (size_t)l * HID, gn_b + (size_t)l * HID,
                                  gn_ms + (size_t)l * HID, (l == 2) ? 1 : 0);
    }

    head_kernel<<<GG, 128>>>(fc_w1, fc_b1, fc_w2, fc_b2, outp);
}